// round 15
// baseline (speedup 1.0000x reference)
#include <cuda_runtime.h>
#include <cuda_bf16.h>
#include <cuda_fp16.h>

// ---------------------------------------------------------------------------
// UFF energy -> out[8]. Coords batch-major fp16 half4: g_h[atom*8+b].
// 4 lanes x 2 batches per term (uint4 coord loads = 2 batches per load).
// R15 = R14 structure (vdw|torsion|angle|bond|inversion, R10 depths) with:
//   - __launch_bounds__(256, 5): let ptxas use up to 51 regs (was self-capped
//     at 40, limiting staged-chain depth to ~2.5 of the 4 vdW chains)
//   - explicitly staged vdW quad: 4 idx loads -> 8 coord gathers -> params
//     -> math, so all four idx->coord chains are front-batched in flight.
// ---------------------------------------------------------------------------

#define NBATCH 8
#define MAX_ATOMS 50000

__device__ uint2 g_h[MAX_ATOMS * NBATCH];   // [atom][batch] half4 (8B)

__device__ __forceinline__ float clip1(float x) {
    return fminf(fmaxf(x, -0.999999f), 0.999999f);
}

__device__ __forceinline__ __half2 u2h(unsigned u) {
    return *reinterpret_cast<__half2*>(&u);
}

// load both batches (2*bp, 2*bp+1) of one atom: 16B
__device__ __forceinline__ uint4 ldco2(int atom, int bp) {
    const uint4* g4 = reinterpret_cast<const uint4*>(g_h);
    return __ldg(&g4[atom * 4 + bp]);
}

// d0,d1 = per-batch (a - c) differences, computed in half2 then widened
__device__ __forceinline__ void hdiff2(uint4 a, uint4 c, float3& d0, float3& d1) {
    __half2 dxy0 = __hsub2(u2h(a.x), u2h(c.x));
    __half2 dz0  = __hsub2(u2h(a.y), u2h(c.y));
    __half2 dxy1 = __hsub2(u2h(a.z), u2h(c.z));
    __half2 dz1  = __hsub2(u2h(a.w), u2h(c.w));
    float2 f0 = __half22float2(dxy0);
    float2 f1 = __half22float2(dxy1);
    d0 = make_float3(f0.x, f0.y, __low2float(dz0));
    d1 = make_float3(f1.x, f1.y, __low2float(dz1));
}

// ---------------------------------------------------------------------------
// pack coords (B,N,3) f32 -> batch-major half4; zero out[8]
// ---------------------------------------------------------------------------
__global__ void pack_kernel(const float* __restrict__ coords,
                            float* __restrict__ out, int natoms) {
    int i = blockIdx.x * blockDim.x + threadIdx.x;
    if (i < NBATCH) out[i] = 0.0f;
    if (i < natoms * NBATCH) {
        int atom = i >> 3;
        int b    = i & 7;
        size_t src = ((size_t)b * natoms + atom) * 3;
        __half2 hxy = __floats2half2_rn(coords[src], coords[src + 1]);
        __half2 hz  = __floats2half2_rn(coords[src + 2], 0.0f);
        uint2 u;
        u.x = *reinterpret_cast<unsigned*>(&hxy);
        u.y = *reinterpret_cast<unsigned*>(&hz);
        g_h[i] = u;
    }
}

// ---------------------------------------------------------------------------
// reduction: thread holds e0 (batch 2*bp) and e1 (batch 2*bp+1), bp = lane&3
// ---------------------------------------------------------------------------
__device__ __forceinline__ void reduce_out2(float e0, float e1,
                                            float* __restrict__ out) {
    #pragma unroll
    for (int off = 16; off >= 4; off >>= 1) {
        e0 += __shfl_down_sync(0xFFFFFFFFu, e0, off);
        e1 += __shfl_down_sync(0xFFFFFFFFu, e1, off);
    }
    __shared__ float s[NBATCH];
    if (threadIdx.x < NBATCH) s[threadIdx.x] = 0.0f;
    __syncthreads();
    if ((threadIdx.x & 31) < 4) {
        int bp = threadIdx.x & 3;
        atomicAdd(&s[2 * bp],     e0);
        atomicAdd(&s[2 * bp + 1], e1);
    }
    __syncthreads();
    if (threadIdx.x < NBATCH) atomicAdd(&out[threadIdx.x], s[threadIdx.x]);
}

// ---------------------------------------------------------------------------
// fp32 fallback distance^2 for near-collision vdW pairs
// ---------------------------------------------------------------------------
__device__ __forceinline__ float d2_fp32(const float* __restrict__ coords,
                                         int natoms, int b, int2 p) {
    size_t sa = ((size_t)b * natoms + p.x) * 3;
    size_t sc = ((size_t)b * natoms + p.y) * 3;
    float dx = __ldg(&coords[sa])     - __ldg(&coords[sc]);
    float dy = __ldg(&coords[sa + 1]) - __ldg(&coords[sc + 1]);
    float dz = __ldg(&coords[sa + 2]) - __ldg(&coords[sc + 2]);
    return fmaf(dx, dx, fmaf(dy, dy, dz * dz));
}

__device__ __forceinline__ float lj(float d2, float R2, float D, float t2) {
    float x2 = R2 * __fdividef(1.0f, fmaxf(d2, 1e-12f));
    float x6 = x2 * x2 * x2;
    float ep = D * fmaf(x6, x6, -2.0f * x6);
    return (d2 <= t2) ? ep : 0.0f;
}

// ---------------------------------------------------------------------------
// term bodies (each evaluates batches 2*bp and 2*bp+1)
// ---------------------------------------------------------------------------
__device__ __forceinline__ void vdw_body(
    int t, int bp, const int2* __restrict__ cidx, const float* __restrict__ cR,
    const float* __restrict__ cD, const float* __restrict__ cT,
    const float* __restrict__ coords, int natoms, float& e0, float& e1)
{
    int2  p  = __ldg(&cidx[t]);
    float R  = __ldg(&cR[t]);
    float D  = __ldg(&cD[t]);
    float t2 = __ldg(&cT[t]);
    uint4 A = ldco2(p.x, bp);
    uint4 C = ldco2(p.y, bp);
    float3 d0, d1;
    hdiff2(A, C, d0, d1);
    float d20 = fmaf(d0.x, d0.x, fmaf(d0.y, d0.y, d0.z * d0.z));
    float d21 = fmaf(d1.x, d1.x, fmaf(d1.y, d1.y, d1.z * d1.z));
    if (d20 < 4.0f) d20 = d2_fp32(coords, natoms, 2 * bp,     p);
    if (d21 < 4.0f) d21 = d2_fp32(coords, natoms, 2 * bp + 1, p);
    float R2 = R * R;
    e0 += lj(d20, R2, D, t2);
    e1 += lj(d21, R2, D, t2);
}

__device__ __forceinline__ float tor_e(float3 b1, float3 b2, float3 b3,
                                       float V2, int ord, float ctm) {
    float n1x = b1.y * b2.z - b1.z * b2.y;
    float n1y = b1.z * b2.x - b1.x * b2.z;
    float n1z = b1.x * b2.y - b1.y * b2.x;
    float n2x = b2.y * b3.z - b2.z * b3.y;
    float n2y = b2.z * b3.x - b2.x * b3.z;
    float n2z = b2.x * b3.y - b2.y * b3.x;
    float dot = fmaf(n1x, n2x, fmaf(n1y, n2y, n1z * n2z));
    float m1  = fmaf(n1x, n1x, fmaf(n1y, n1y, n1z * n1z));
    float m2  = fmaf(n2x, n2x, fmaf(n2y, n2y, n2z * n2z));
    float c   = clip1(dot * rsqrtf(fmaxf(m1 * m2, 1e-24f)));
    float c2 = 2.0f * c;
    float T1 = c;
    float T2 = fmaf(c2, T1, -1.0f);
    float T3 = fmaf(c2, T2, -T1);
    float T4 = fmaf(c2, T3, -T2);
    float T5 = fmaf(c2, T4, -T3);
    float T6 = fmaf(c2, T5, -T4);
    float Tn = (ord <= 1) ? T1 : (ord == 2) ? T2 : (ord == 3) ? T3
             : (ord == 4) ? T4 : (ord == 5) ? T5 : T6;
    return V2 * (1.0f - ctm * Tn);
}

__device__ __forceinline__ void torsion_body(
    int t, int bp, const int4* __restrict__ tidx, const float* __restrict__ tk,
    const int* __restrict__ tord, const float* __restrict__ tcos,
    float& e0, float& e1)
{
    int4  q   = __ldg(&tidx[t]);
    float V2  = 0.5f * __ldg(&tk[t]);
    int   ord = __ldg(&tord[t]);
    float ctm = __ldg(&tcos[t]);
    uint4 q1 = ldco2(q.x, bp);
    uint4 q2 = ldco2(q.y, bp);
    uint4 q3 = ldco2(q.z, bp);
    uint4 q4 = ldco2(q.w, bp);
    float3 b1a, b1b, b2a, b2b, b3a, b3b;
    hdiff2(q2, q1, b1a, b1b);
    hdiff2(q3, q2, b2a, b2b);
    hdiff2(q4, q3, b3a, b3b);
    e0 += tor_e(b1a, b2a, b3a, V2, ord, ctm);
    e1 += tor_e(b1b, b2b, b3b, V2, ord, ctm);
}

__device__ __forceinline__ void angle_body(
    int t, int bp, const int* __restrict__ aidx, const float* __restrict__ ak,
    const float* __restrict__ ac0, const float* __restrict__ ac1,
    const float* __restrict__ ac2, float& e0, float& e1)
{
    int i0 = __ldg(&aidx[3 * t + 0]);
    int i1 = __ldg(&aidx[3 * t + 1]);
    int i2 = __ldg(&aidx[3 * t + 2]);
    float K  = __ldg(&ak[t]);
    float a0 = __ldg(&ac0[t]);
    float a1 = __ldg(&ac1[t]);
    float a2 = __ldg(&ac2[t]);
    uint4 p1 = ldco2(i0, bp);
    uint4 p2 = ldco2(i1, bp);
    uint4 p3 = ldco2(i2, bp);
    float3 v1a, v1b, v2a, v2b;
    hdiff2(p1, p2, v1a, v1b);
    hdiff2(p3, p2, v2a, v2b);
    #pragma unroll
    for (int s = 0; s < 2; s++) {
        float3 v1 = s ? v1b : v1a;
        float3 v2 = s ? v2b : v2a;
        float dot = fmaf(v1.x, v2.x, fmaf(v1.y, v2.y, v1.z * v2.z));
        float n1  = fmaf(v1.x, v1.x, fmaf(v1.y, v1.y, v1.z * v1.z));
        float n2  = fmaf(v2.x, v2.x, fmaf(v2.y, v2.y, v2.z * v2.z));
        float ct  = clip1(dot * rsqrtf(fmaxf(n1 * n2, 1e-24f)));
        float cs  = ct * ct;
        float ss  = fmaxf(1.0f - cs, 1e-12f);
        float ee  = K * fmaf(a2, cs - ss, fmaf(a1, ct, a0));
        if (s) e1 += ee; else e0 += ee;
    }
}

__device__ __forceinline__ void bond_body(
    int t, int bp, const int2* __restrict__ bidx, const float* __restrict__ br0,
    const float* __restrict__ bk, float& e0, float& e1)
{
    int2  p  = __ldg(&bidx[t]);
    float r0 = __ldg(&br0[t]);
    float k2 = 0.5f * __ldg(&bk[t]);
    uint4 A = ldco2(p.x, bp);
    uint4 C = ldco2(p.y, bp);
    float3 d0, d1;
    hdiff2(A, C, d0, d1);
    float s0 = fmaxf(fmaf(d0.x, d0.x, fmaf(d0.y, d0.y, d0.z * d0.z)), 1e-24f);
    float s1 = fmaxf(fmaf(d1.x, d1.x, fmaf(d1.y, d1.y, d1.z * d1.z)), 1e-24f);
    float dd0 = s0 * rsqrtf(s0) - r0;   // sqrt(s0) - r0
    float dd1 = s1 * rsqrtf(s1) - r0;
    e0 += k2 * dd0 * dd0;
    e1 += k2 * dd1 * dd1;
}

// ---------------------------------------------------------------------------
// fused term kernel: vdw | torsion | angle | bond | inversion by block range
// (R10 order). 256 threads = 64 term-groups x 4 lanes x 2 batches.
// launch_bounds(256, 5): allow up to 51 regs for deeper staged chains.
// ---------------------------------------------------------------------------
__global__ __launch_bounds__(256, 5)
void fused_kernel(
    const float* __restrict__ coords,
    const int2* __restrict__ cidx, const float* __restrict__ cR,
    const float* __restrict__ cD,  const float* __restrict__ cT,
    int nc, int cBlocks,
    const int4* __restrict__ tidx, const float* __restrict__ tk,
    const int* __restrict__ tord,  const float* __restrict__ tcos,
    int nt, int tBlocks,
    const int* __restrict__ aidx,  const float* __restrict__ ak,
    const float* __restrict__ ac0, const float* __restrict__ ac1,
    const float* __restrict__ ac2, int na, int aBlocks,
    const int2* __restrict__ bidx, const float* __restrict__ br0,
    const float* __restrict__ bk,  int nb, int bBlocks,
    const int4* __restrict__ iidx, const float* __restrict__ ik,
    const float* __restrict__ ic0, const float* __restrict__ ic1,
    const float* __restrict__ ic2, int ni, int iBlocks,
    int natoms, float* __restrict__ out)
{
    const int blk = blockIdx.x;
    const int bp  = threadIdx.x & 3;   // batch pair (batches 2bp, 2bp+1)
    const int grp = threadIdx.x >> 2;  // term-group (0..63)
    float e0 = 0.0f, e1 = 0.0f;

    if (blk < cBlocks) {
        // ---------------- vdW LJ (staged QUAD-chain) ----------------
        const int stride = cBlocks * 64;
        int t = blk * 64 + grp;
        for (; t + 3 * stride < nc; t += 4 * stride) {
            // phase 1: all 4 index loads in flight
            int2 P0 = __ldg(&cidx[t]);
            int2 P1 = __ldg(&cidx[t + stride]);
            int2 P2 = __ldg(&cidx[t + 2 * stride]);
            int2 P3 = __ldg(&cidx[t + 3 * stride]);
            // phase 2: all 8 coord gathers in flight
            uint4 A0 = ldco2(P0.x, bp), C0 = ldco2(P0.y, bp);
            uint4 A1 = ldco2(P1.x, bp), C1 = ldco2(P1.y, bp);
            uint4 A2 = ldco2(P2.x, bp), C2 = ldco2(P2.y, bp);
            uint4 A3 = ldco2(P3.x, bp), C3 = ldco2(P3.y, bp);
            // phase 3: params (streamed, overlap with coord latency)
            float R0 = __ldg(&cR[t]),              D0 = __ldg(&cD[t]),              T0 = __ldg(&cT[t]);
            float R1 = __ldg(&cR[t + stride]),     D1 = __ldg(&cD[t + stride]),     T1 = __ldg(&cT[t + stride]);
            float R2_ = __ldg(&cR[t + 2 * stride]), D2 = __ldg(&cD[t + 2 * stride]), T2 = __ldg(&cT[t + 2 * stride]);
            float R3 = __ldg(&cR[t + 3 * stride]), D3 = __ldg(&cD[t + 3 * stride]), T3 = __ldg(&cT[t + 3 * stride]);
            // phase 4: math
            {
                float3 d0, d1;
                hdiff2(A0, C0, d0, d1);
                float d20 = fmaf(d0.x, d0.x, fmaf(d0.y, d0.y, d0.z * d0.z));
                float d21 = fmaf(d1.x, d1.x, fmaf(d1.y, d1.y, d1.z * d1.z));
                if (d20 < 4.0f) d20 = d2_fp32(coords, natoms, 2 * bp,     P0);
                if (d21 < 4.0f) d21 = d2_fp32(coords, natoms, 2 * bp + 1, P0);
                float Rq = R0 * R0;
                e0 += lj(d20, Rq, D0, T0);
                e1 += lj(d21, Rq, D0, T0);
            }
            {
                float3 d0, d1;
                hdiff2(A1, C1, d0, d1);
                float d20 = fmaf(d0.x, d0.x, fmaf(d0.y, d0.y, d0.z * d0.z));
                float d21 = fmaf(d1.x, d1.x, fmaf(d1.y, d1.y, d1.z * d1.z));
                if (d20 < 4.0f) d20 = d2_fp32(coords, natoms, 2 * bp,     P1);
                if (d21 < 4.0f) d21 = d2_fp32(coords, natoms, 2 * bp + 1, P1);
                float Rq = R1 * R1;
                e0 += lj(d20, Rq, D1, T1);
                e1 += lj(d21, Rq, D1, T1);
            }
            {
                float3 d0, d1;
                hdiff2(A2, C2, d0, d1);
                float d20 = fmaf(d0.x, d0.x, fmaf(d0.y, d0.y, d0.z * d0.z));
                float d21 = fmaf(d1.x, d1.x, fmaf(d1.y, d1.y, d1.z * d1.z));
                if (d20 < 4.0f) d20 = d2_fp32(coords, natoms, 2 * bp,     P2);
                if (d21 < 4.0f) d21 = d2_fp32(coords, natoms, 2 * bp + 1, P2);
                float Rq = R2_ * R2_;
                e0 += lj(d20, Rq, D2, T2);
                e1 += lj(d21, Rq, D2, T2);
            }
            {
                float3 d0, d1;
                hdiff2(A3, C3, d0, d1);
                float d20 = fmaf(d0.x, d0.x, fmaf(d0.y, d0.y, d0.z * d0.z));
                float d21 = fmaf(d1.x, d1.x, fmaf(d1.y, d1.y, d1.z * d1.z));
                if (d20 < 4.0f) d20 = d2_fp32(coords, natoms, 2 * bp,     P3);
                if (d21 < 4.0f) d21 = d2_fp32(coords, natoms, 2 * bp + 1, P3);
                float Rq = R3 * R3;
                e0 += lj(d20, Rq, D3, T3);
                e1 += lj(d21, Rq, D3, T3);
            }
        }
        for (; t < nc; t += stride)
            vdw_body(t, bp, cidx, cR, cD, cT, coords, natoms, e0, e1);
    } else if (blk < cBlocks + tBlocks) {
        // ---------------- torsion (dual-chain) ----------------
        const int stride = tBlocks * 64;
        int t = (blk - cBlocks) * 64 + grp;
        for (; t + stride < nt; t += 2 * stride) {
            torsion_body(t,          bp, tidx, tk, tord, tcos, e0, e1);
            torsion_body(t + stride, bp, tidx, tk, tord, tcos, e0, e1);
        }
        if (t < nt)
            torsion_body(t, bp, tidx, tk, tord, tcos, e0, e1);
    } else if (blk < cBlocks + tBlocks + aBlocks) {
        // ---------------- angle (dual-chain) ----------------
        const int base = cBlocks + tBlocks, stride = aBlocks * 64;
        int t = (blk - base) * 64 + grp;
        for (; t + stride < na; t += 2 * stride) {
            angle_body(t,          bp, aidx, ak, ac0, ac1, ac2, e0, e1);
            angle_body(t + stride, bp, aidx, ak, ac0, ac1, ac2, e0, e1);
        }
        if (t < na)
            angle_body(t, bp, aidx, ak, ac0, ac1, ac2, e0, e1);
    } else if (blk < cBlocks + tBlocks + aBlocks + bBlocks) {
        // ---------------- bond (dual-chain) ----------------
        const int base = cBlocks + tBlocks + aBlocks, stride = bBlocks * 64;
        int t = (blk - base) * 64 + grp;
        for (; t + stride < nb; t += 2 * stride) {
            bond_body(t,          bp, bidx, br0, bk, e0, e1);
            bond_body(t + stride, bp, bidx, br0, bk, e0, e1);
        }
        if (t < nb)
            bond_body(t, bp, bidx, br0, bk, e0, e1);
    } else {
        // ---------------- inversion ----------------
        const int base = cBlocks + tBlocks + aBlocks + bBlocks, stride = iBlocks * 64;
        for (int t = (blk - base) * 64 + grp; t < ni; t += stride) {
            int4  q  = __ldg(&iidx[t]);
            float K  = __ldg(&ik[t]);
            float a0 = __ldg(&ic0[t]);
            float a1 = __ldg(&ic1[t]);
            float a2 = __ldg(&ic2[t]);
            uint4 pi = ldco2(q.x, bp);
            uint4 pj = ldco2(q.y, bp);  // central
            uint4 pk = ldco2(q.z, bp);
            uint4 pl = ldco2(q.w, bp);
            float3 ia, ib, ka, kb, la, lb;
            hdiff2(pi, pj, ia, ib);
            hdiff2(pk, pj, ka, kb);
            hdiff2(pl, pj, la, lb);
            #pragma unroll
            for (int s = 0; s < 2; s++) {
                float3 vi = s ? ib : ia;
                float3 vk = s ? kb : ka;
                float3 vl = s ? lb : la;
                float nx = vi.y * vk.z - vi.z * vk.y;
                float ny = vi.z * vk.x - vi.x * vk.z;
                float nz = vi.x * vk.y - vi.y * vk.x;
                float dot = fmaf(nx, vl.x, fmaf(ny, vl.y, nz * vl.z));
                float m1  = fmaf(nx, nx, fmaf(ny, ny, nz * nz));
                float m2  = fmaf(vl.x, vl.x, fmaf(vl.y, vl.y, vl.z * vl.z));
                float cosY = clip1(dot * rsqrtf(fmaxf(m1 * m2, 1e-24f)));
                float s2 = fmaxf(1.0f - cosY * cosY, 1e-24f);
                float sinY = s2 * rsqrtf(s2);  // sqrt
                float ee = K * fmaf(a2, fmaf(2.0f * sinY, sinY, -1.0f), fmaf(a1, sinY, a0));
                if (s) e1 += ee; else e0 += ee;
            }
        }
    }

    reduce_out2(e0, e1, out);
}

// ---------------------------------------------------------------------------
// launch
// ---------------------------------------------------------------------------
static inline int blocks_for(int n_terms, int iters) {
    long long groups = ((long long)n_terms + 64LL * iters - 1) / (64LL * iters);
    return groups < 1 ? 1 : (int)groups;
}

extern "C" void kernel_launch(void* const* d_in, const int* in_sizes, int n_in,
                              void* d_out, int out_size) {
    const float* coords      = (const float*)d_in[0];
    const int*   bond_index  = (const int*)d_in[1];
    const float* bond_r0     = (const float*)d_in[2];
    const float* bond_k      = (const float*)d_in[3];
    const int*   angle_index = (const int*)d_in[4];
    const float* angle_k     = (const float*)d_in[5];
    const float* angle_c0    = (const float*)d_in[6];
    const float* angle_c1    = (const float*)d_in[7];
    const float* angle_c2    = (const float*)d_in[8];
    const int*   tor_index   = (const int*)d_in[9];
    const float* tor_k       = (const float*)d_in[10];
    const int*   tor_order   = (const int*)d_in[11];
    const float* tor_cos     = (const float*)d_in[12];
    const int*   inv_index   = (const int*)d_in[13];
    const float* inv_k       = (const float*)d_in[14];
    const float* inv_c0      = (const float*)d_in[15];
    const float* inv_c1      = (const float*)d_in[16];
    const float* inv_c2      = (const float*)d_in[17];
    const int*   nb_index    = (const int*)d_in[18];
    const float* vdw_min     = (const float*)d_in[19];
    const float* vdw_depth   = (const float*)d_in[20];
    const float* vdw_thr     = (const float*)d_in[21];
    float* out = (float*)d_out;

    const int NB = in_sizes[1]  / 2;
    const int NA = in_sizes[4]  / 3;
    const int NT = in_sizes[9]  / 4;
    const int NI = in_sizes[13] / 4;
    const int NC = in_sizes[18] / 2;
    const int natoms = in_sizes[0] / (3 * NBATCH);  // B fixed = 8
    const int total  = NBATCH * natoms;

    const int T = 256;
    pack_kernel<<<(total + T - 1) / T, T>>>(coords, out, natoms);

    // R10 block depths (proven 39.4us configuration)
    const int cB = blocks_for(NC, 4);
    const int tB = blocks_for(NT, 2);
    const int aB = blocks_for(NA, 2);
    const int bB = blocks_for(NB, 1);
    const int iB = blocks_for(NI, 1);
    const int grid = cB + tB + aB + bB + iB;

    fused_kernel<<<grid, T>>>(
        coords,
        (const int2*)nb_index, vdw_min, vdw_depth, vdw_thr, NC, cB,
        (const int4*)tor_index, tor_k, tor_order, tor_cos, NT, tB,
        angle_index, angle_k, angle_c0, angle_c1, angle_c2, NA, aB,
        (const int2*)bond_index, bond_r0, bond_k, NB, bB,
        (const int4*)inv_index, inv_k, inv_c0, inv_c1, inv_c2, NI, iB,
        natoms, out);
}

// round 16
// speedup vs baseline: 1.2819x; 1.2819x over previous
#include <cuda_runtime.h>
#include <cuda_bf16.h>
#include <cuda_fp16.h>

// ---------------------------------------------------------------------------
// UFF energy -> out[8]. Coords batch-major fp16 half4: g_h[atom*8+b].
// 4 lanes x 2 batches per term (uint4 coord loads = 2 batches per load).
// R16 = R14 exactly (the proven 39.4us config: segment order
// vdw|torsion|angle|bond|inversion, 40-reg ptxas schedule) with ONE change:
// vdW grid-stride depth 4 -> 8, so each vdW block runs the quad loop twice
// (cross-iteration pipelining, fewer block prologues, short-block tail).
// ---------------------------------------------------------------------------

#define NBATCH 8
#define MAX_ATOMS 50000

__device__ uint2 g_h[MAX_ATOMS * NBATCH];   // [atom][batch] half4 (8B)

__device__ __forceinline__ float clip1(float x) {
    return fminf(fmaxf(x, -0.999999f), 0.999999f);
}

__device__ __forceinline__ __half2 u2h(unsigned u) {
    return *reinterpret_cast<__half2*>(&u);
}

// load both batches (2*bp, 2*bp+1) of one atom: 16B
__device__ __forceinline__ uint4 ldco2(int atom, int bp) {
    const uint4* g4 = reinterpret_cast<const uint4*>(g_h);
    return __ldg(&g4[atom * 4 + bp]);
}

// d0,d1 = per-batch (a - c) differences, computed in half2 then widened
__device__ __forceinline__ void hdiff2(uint4 a, uint4 c, float3& d0, float3& d1) {
    __half2 dxy0 = __hsub2(u2h(a.x), u2h(c.x));
    __half2 dz0  = __hsub2(u2h(a.y), u2h(c.y));
    __half2 dxy1 = __hsub2(u2h(a.z), u2h(c.z));
    __half2 dz1  = __hsub2(u2h(a.w), u2h(c.w));
    float2 f0 = __half22float2(dxy0);
    float2 f1 = __half22float2(dxy1);
    d0 = make_float3(f0.x, f0.y, __low2float(dz0));
    d1 = make_float3(f1.x, f1.y, __low2float(dz1));
}

// ---------------------------------------------------------------------------
// pack coords (B,N,3) f32 -> batch-major half4; zero out[8]
// ---------------------------------------------------------------------------
__global__ void pack_kernel(const float* __restrict__ coords,
                            float* __restrict__ out, int natoms) {
    int i = blockIdx.x * blockDim.x + threadIdx.x;
    if (i < NBATCH) out[i] = 0.0f;
    if (i < natoms * NBATCH) {
        int atom = i >> 3;
        int b    = i & 7;
        size_t src = ((size_t)b * natoms + atom) * 3;
        __half2 hxy = __floats2half2_rn(coords[src], coords[src + 1]);
        __half2 hz  = __floats2half2_rn(coords[src + 2], 0.0f);
        uint2 u;
        u.x = *reinterpret_cast<unsigned*>(&hxy);
        u.y = *reinterpret_cast<unsigned*>(&hz);
        g_h[i] = u;
    }
}

// ---------------------------------------------------------------------------
// reduction: thread holds e0 (batch 2*bp) and e1 (batch 2*bp+1), bp = lane&3
// ---------------------------------------------------------------------------
__device__ __forceinline__ void reduce_out2(float e0, float e1,
                                            float* __restrict__ out) {
    #pragma unroll
    for (int off = 16; off >= 4; off >>= 1) {
        e0 += __shfl_down_sync(0xFFFFFFFFu, e0, off);
        e1 += __shfl_down_sync(0xFFFFFFFFu, e1, off);
    }
    __shared__ float s[NBATCH];
    if (threadIdx.x < NBATCH) s[threadIdx.x] = 0.0f;
    __syncthreads();
    if ((threadIdx.x & 31) < 4) {
        int bp = threadIdx.x & 3;
        atomicAdd(&s[2 * bp],     e0);
        atomicAdd(&s[2 * bp + 1], e1);
    }
    __syncthreads();
    if (threadIdx.x < NBATCH) atomicAdd(&out[threadIdx.x], s[threadIdx.x]);
}

// ---------------------------------------------------------------------------
// fp32 fallback distance^2 for near-collision vdW pairs
// ---------------------------------------------------------------------------
__device__ __forceinline__ float d2_fp32(const float* __restrict__ coords,
                                         int natoms, int b, int2 p) {
    size_t sa = ((size_t)b * natoms + p.x) * 3;
    size_t sc = ((size_t)b * natoms + p.y) * 3;
    float dx = __ldg(&coords[sa])     - __ldg(&coords[sc]);
    float dy = __ldg(&coords[sa + 1]) - __ldg(&coords[sc + 1]);
    float dz = __ldg(&coords[sa + 2]) - __ldg(&coords[sc + 2]);
    return fmaf(dx, dx, fmaf(dy, dy, dz * dz));
}

__device__ __forceinline__ float lj(float d2, float R2, float D, float t2) {
    float x2 = R2 * __fdividef(1.0f, fmaxf(d2, 1e-12f));
    float x6 = x2 * x2 * x2;
    float ep = D * fmaf(x6, x6, -2.0f * x6);
    return (d2 <= t2) ? ep : 0.0f;
}

// ---------------------------------------------------------------------------
// term bodies (each evaluates batches 2*bp and 2*bp+1)
// ---------------------------------------------------------------------------
__device__ __forceinline__ void vdw_body(
    int t, int bp, const int2* __restrict__ cidx, const float* __restrict__ cR,
    const float* __restrict__ cD, const float* __restrict__ cT,
    const float* __restrict__ coords, int natoms, float& e0, float& e1)
{
    int2  p  = __ldg(&cidx[t]);
    float R  = __ldg(&cR[t]);
    float D  = __ldg(&cD[t]);
    float t2 = __ldg(&cT[t]);
    uint4 A = ldco2(p.x, bp);
    uint4 C = ldco2(p.y, bp);
    float3 d0, d1;
    hdiff2(A, C, d0, d1);
    float d20 = fmaf(d0.x, d0.x, fmaf(d0.y, d0.y, d0.z * d0.z));
    float d21 = fmaf(d1.x, d1.x, fmaf(d1.y, d1.y, d1.z * d1.z));
    if (d20 < 4.0f) d20 = d2_fp32(coords, natoms, 2 * bp,     p);
    if (d21 < 4.0f) d21 = d2_fp32(coords, natoms, 2 * bp + 1, p);
    float R2 = R * R;
    e0 += lj(d20, R2, D, t2);
    e1 += lj(d21, R2, D, t2);
}

__device__ __forceinline__ float tor_e(float3 b1, float3 b2, float3 b3,
                                       float V2, int ord, float ctm) {
    float n1x = b1.y * b2.z - b1.z * b2.y;
    float n1y = b1.z * b2.x - b1.x * b2.z;
    float n1z = b1.x * b2.y - b1.y * b2.x;
    float n2x = b2.y * b3.z - b2.z * b3.y;
    float n2y = b2.z * b3.x - b2.x * b3.z;
    float n2z = b2.x * b3.y - b2.y * b3.x;
    float dot = fmaf(n1x, n2x, fmaf(n1y, n2y, n1z * n2z));
    float m1  = fmaf(n1x, n1x, fmaf(n1y, n1y, n1z * n1z));
    float m2  = fmaf(n2x, n2x, fmaf(n2y, n2y, n2z * n2z));
    float c   = clip1(dot * rsqrtf(fmaxf(m1 * m2, 1e-24f)));
    float c2 = 2.0f * c;
    float T1 = c;
    float T2 = fmaf(c2, T1, -1.0f);
    float T3 = fmaf(c2, T2, -T1);
    float T4 = fmaf(c2, T3, -T2);
    float T5 = fmaf(c2, T4, -T3);
    float T6 = fmaf(c2, T5, -T4);
    float Tn = (ord <= 1) ? T1 : (ord == 2) ? T2 : (ord == 3) ? T3
             : (ord == 4) ? T4 : (ord == 5) ? T5 : T6;
    return V2 * (1.0f - ctm * Tn);
}

__device__ __forceinline__ void torsion_body(
    int t, int bp, const int4* __restrict__ tidx, const float* __restrict__ tk,
    const int* __restrict__ tord, const float* __restrict__ tcos,
    float& e0, float& e1)
{
    int4  q   = __ldg(&tidx[t]);
    float V2  = 0.5f * __ldg(&tk[t]);
    int   ord = __ldg(&tord[t]);
    float ctm = __ldg(&tcos[t]);
    uint4 q1 = ldco2(q.x, bp);
    uint4 q2 = ldco2(q.y, bp);
    uint4 q3 = ldco2(q.z, bp);
    uint4 q4 = ldco2(q.w, bp);
    float3 b1a, b1b, b2a, b2b, b3a, b3b;
    hdiff2(q2, q1, b1a, b1b);
    hdiff2(q3, q2, b2a, b2b);
    hdiff2(q4, q3, b3a, b3b);
    e0 += tor_e(b1a, b2a, b3a, V2, ord, ctm);
    e1 += tor_e(b1b, b2b, b3b, V2, ord, ctm);
}

__device__ __forceinline__ void angle_body(
    int t, int bp, const int* __restrict__ aidx, const float* __restrict__ ak,
    const float* __restrict__ ac0, const float* __restrict__ ac1,
    const float* __restrict__ ac2, float& e0, float& e1)
{
    int i0 = __ldg(&aidx[3 * t + 0]);
    int i1 = __ldg(&aidx[3 * t + 1]);
    int i2 = __ldg(&aidx[3 * t + 2]);
    float K  = __ldg(&ak[t]);
    float a0 = __ldg(&ac0[t]);
    float a1 = __ldg(&ac1[t]);
    float a2 = __ldg(&ac2[t]);
    uint4 p1 = ldco2(i0, bp);
    uint4 p2 = ldco2(i1, bp);
    uint4 p3 = ldco2(i2, bp);
    float3 v1a, v1b, v2a, v2b;
    hdiff2(p1, p2, v1a, v1b);
    hdiff2(p3, p2, v2a, v2b);
    #pragma unroll
    for (int s = 0; s < 2; s++) {
        float3 v1 = s ? v1b : v1a;
        float3 v2 = s ? v2b : v2a;
        float dot = fmaf(v1.x, v2.x, fmaf(v1.y, v2.y, v1.z * v2.z));
        float n1  = fmaf(v1.x, v1.x, fmaf(v1.y, v1.y, v1.z * v1.z));
        float n2  = fmaf(v2.x, v2.x, fmaf(v2.y, v2.y, v2.z * v2.z));
        float ct  = clip1(dot * rsqrtf(fmaxf(n1 * n2, 1e-24f)));
        float cs  = ct * ct;
        float ss  = fmaxf(1.0f - cs, 1e-12f);
        float ee  = K * fmaf(a2, cs - ss, fmaf(a1, ct, a0));
        if (s) e1 += ee; else e0 += ee;
    }
}

__device__ __forceinline__ void bond_body(
    int t, int bp, const int2* __restrict__ bidx, const float* __restrict__ br0,
    const float* __restrict__ bk, float& e0, float& e1)
{
    int2  p  = __ldg(&bidx[t]);
    float r0 = __ldg(&br0[t]);
    float k2 = 0.5f * __ldg(&bk[t]);
    uint4 A = ldco2(p.x, bp);
    uint4 C = ldco2(p.y, bp);
    float3 d0, d1;
    hdiff2(A, C, d0, d1);
    float s0 = fmaxf(fmaf(d0.x, d0.x, fmaf(d0.y, d0.y, d0.z * d0.z)), 1e-24f);
    float s1 = fmaxf(fmaf(d1.x, d1.x, fmaf(d1.y, d1.y, d1.z * d1.z)), 1e-24f);
    float dd0 = s0 * rsqrtf(s0) - r0;   // sqrt(s0) - r0
    float dd1 = s1 * rsqrtf(s1) - r0;
    e0 += k2 * dd0 * dd0;
    e1 += k2 * dd1 * dd1;
}

// ---------------------------------------------------------------------------
// fused term kernel: vdw | torsion | angle | bond | inversion by block range
// (R10 order). 256 threads = 64 term-groups x 4 lanes x 2 batches.
// ---------------------------------------------------------------------------
__global__ __launch_bounds__(256)
void fused_kernel(
    const float* __restrict__ coords,
    const int2* __restrict__ cidx, const float* __restrict__ cR,
    const float* __restrict__ cD,  const float* __restrict__ cT,
    int nc, int cBlocks,
    const int4* __restrict__ tidx, const float* __restrict__ tk,
    const int* __restrict__ tord,  const float* __restrict__ tcos,
    int nt, int tBlocks,
    const int* __restrict__ aidx,  const float* __restrict__ ak,
    const float* __restrict__ ac0, const float* __restrict__ ac1,
    const float* __restrict__ ac2, int na, int aBlocks,
    const int2* __restrict__ bidx, const float* __restrict__ br0,
    const float* __restrict__ bk,  int nb, int bBlocks,
    const int4* __restrict__ iidx, const float* __restrict__ ik,
    const float* __restrict__ ic0, const float* __restrict__ ic1,
    const float* __restrict__ ic2, int ni, int iBlocks,
    int natoms, float* __restrict__ out)
{
    const int blk = blockIdx.x;
    const int bp  = threadIdx.x & 3;   // batch pair (batches 2bp, 2bp+1)
    const int grp = threadIdx.x >> 2;  // term-group (0..63)
    float e0 = 0.0f, e1 = 0.0f;

    if (blk < cBlocks) {
        // ---------------- vdW LJ (QUAD-chain, 2 quad-iterations) ----------
        const int stride = cBlocks * 64;
        int t = blk * 64 + grp;
        for (; t + 3 * stride < nc; t += 4 * stride) {
            vdw_body(t,              bp, cidx, cR, cD, cT, coords, natoms, e0, e1);
            vdw_body(t + stride,     bp, cidx, cR, cD, cT, coords, natoms, e0, e1);
            vdw_body(t + 2 * stride, bp, cidx, cR, cD, cT, coords, natoms, e0, e1);
            vdw_body(t + 3 * stride, bp, cidx, cR, cD, cT, coords, natoms, e0, e1);
        }
        for (; t < nc; t += stride)
            vdw_body(t, bp, cidx, cR, cD, cT, coords, natoms, e0, e1);
    } else if (blk < cBlocks + tBlocks) {
        // ---------------- torsion (dual-chain) ----------------
        const int stride = tBlocks * 64;
        int t = (blk - cBlocks) * 64 + grp;
        for (; t + stride < nt; t += 2 * stride) {
            torsion_body(t,          bp, tidx, tk, tord, tcos, e0, e1);
            torsion_body(t + stride, bp, tidx, tk, tord, tcos, e0, e1);
        }
        if (t < nt)
            torsion_body(t, bp, tidx, tk, tord, tcos, e0, e1);
    } else if (blk < cBlocks + tBlocks + aBlocks) {
        // ---------------- angle (dual-chain) ----------------
        const int base = cBlocks + tBlocks, stride = aBlocks * 64;
        int t = (blk - base) * 64 + grp;
        for (; t + stride < na; t += 2 * stride) {
            angle_body(t,          bp, aidx, ak, ac0, ac1, ac2, e0, e1);
            angle_body(t + stride, bp, aidx, ak, ac0, ac1, ac2, e0, e1);
        }
        if (t < na)
            angle_body(t, bp, aidx, ak, ac0, ac1, ac2, e0, e1);
    } else if (blk < cBlocks + tBlocks + aBlocks + bBlocks) {
        // ---------------- bond (dual-chain) ----------------
        const int base = cBlocks + tBlocks + aBlocks, stride = bBlocks * 64;
        int t = (blk - base) * 64 + grp;
        for (; t + stride < nb; t += 2 * stride) {
            bond_body(t,          bp, bidx, br0, bk, e0, e1);
            bond_body(t + stride, bp, bidx, br0, bk, e0, e1);
        }
        if (t < nb)
            bond_body(t, bp, bidx, br0, bk, e0, e1);
    } else {
        // ---------------- inversion ----------------
        const int base = cBlocks + tBlocks + aBlocks + bBlocks, stride = iBlocks * 64;
        for (int t = (blk - base) * 64 + grp; t < ni; t += stride) {
            int4  q  = __ldg(&iidx[t]);
            float K  = __ldg(&ik[t]);
            float a0 = __ldg(&ic0[t]);
            float a1 = __ldg(&ic1[t]);
            float a2 = __ldg(&ic2[t]);
            uint4 pi = ldco2(q.x, bp);
            uint4 pj = ldco2(q.y, bp);  // central
            uint4 pk = ldco2(q.z, bp);
            uint4 pl = ldco2(q.w, bp);
            float3 ia, ib, ka, kb, la, lb;
            hdiff2(pi, pj, ia, ib);
            hdiff2(pk, pj, ka, kb);
            hdiff2(pl, pj, la, lb);
            #pragma unroll
            for (int s = 0; s < 2; s++) {
                float3 vi = s ? ib : ia;
                float3 vk = s ? kb : ka;
                float3 vl = s ? lb : la;
                float nx = vi.y * vk.z - vi.z * vk.y;
                float ny = vi.z * vk.x - vi.x * vk.z;
                float nz = vi.x * vk.y - vi.y * vk.x;
                float dot = fmaf(nx, vl.x, fmaf(ny, vl.y, nz * vl.z));
                float m1  = fmaf(nx, nx, fmaf(ny, ny, nz * nz));
                float m2  = fmaf(vl.x, vl.x, fmaf(vl.y, vl.y, vl.z * vl.z));
                float cosY = clip1(dot * rsqrtf(fmaxf(m1 * m2, 1e-24f)));
                float s2 = fmaxf(1.0f - cosY * cosY, 1e-24f);
                float sinY = s2 * rsqrtf(s2);  // sqrt
                float ee = K * fmaf(a2, fmaf(2.0f * sinY, sinY, -1.0f), fmaf(a1, sinY, a0));
                if (s) e1 += ee; else e0 += ee;
            }
        }
    }

    reduce_out2(e0, e1, out);
}

// ---------------------------------------------------------------------------
// launch
// ---------------------------------------------------------------------------
static inline int blocks_for(int n_terms, int iters) {
    long long groups = ((long long)n_terms + 64LL * iters - 1) / (64LL * iters);
    return groups < 1 ? 1 : (int)groups;
}

extern "C" void kernel_launch(void* const* d_in, const int* in_sizes, int n_in,
                              void* d_out, int out_size) {
    const float* coords      = (const float*)d_in[0];
    const int*   bond_index  = (const int*)d_in[1];
    const float* bond_r0     = (const float*)d_in[2];
    const float* bond_k      = (const float*)d_in[3];
    const int*   angle_index = (const int*)d_in[4];
    const float* angle_k     = (const float*)d_in[5];
    const float* angle_c0    = (const float*)d_in[6];
    const float* angle_c1    = (const float*)d_in[7];
    const float* angle_c2    = (const float*)d_in[8];
    const int*   tor_index   = (const int*)d_in[9];
    const float* tor_k       = (const float*)d_in[10];
    const int*   tor_order   = (const int*)d_in[11];
    const float* tor_cos     = (const float*)d_in[12];
    const int*   inv_index   = (const int*)d_in[13];
    const float* inv_k       = (const float*)d_in[14];
    const float* inv_c0      = (const float*)d_in[15];
    const float* inv_c1      = (const float*)d_in[16];
    const float* inv_c2      = (const float*)d_in[17];
    const int*   nb_index    = (const int*)d_in[18];
    const float* vdw_min     = (const float*)d_in[19];
    const float* vdw_depth   = (const float*)d_in[20];
    const float* vdw_thr     = (const float*)d_in[21];
    float* out = (float*)d_out;

    const int NB = in_sizes[1]  / 2;
    const int NA = in_sizes[4]  / 3;
    const int NT = in_sizes[9]  / 4;
    const int NI = in_sizes[13] / 4;
    const int NC = in_sizes[18] / 2;
    const int natoms = in_sizes[0] / (3 * NBATCH);  // B fixed = 8
    const int total  = NBATCH * natoms;

    const int T = 256;
    pack_kernel<<<(total + T - 1) / T, T>>>(coords, out, natoms);

    // R14 depths except vdW: 4 -> 8 (each vdW block runs the quad loop twice)
    const int cB = blocks_for(NC, 8);
    const int tB = blocks_for(NT, 2);
    const int aB = blocks_for(NA, 2);
    const int bB = blocks_for(NB, 1);
    const int iB = blocks_for(NI, 1);
    const int grid = cB + tB + aB + bB + iB;

    fused_kernel<<<grid, T>>>(
        coords,
        (const int2*)nb_index, vdw_min, vdw_depth, vdw_thr, NC, cB,
        (const int4*)tor_index, tor_k, tor_order, tor_cos, NT, tB,
        angle_index, angle_k, angle_c0, angle_c1, angle_c2, NA, aB,
        (const int2*)bond_index, bond_r0, bond_k, NB, bB,
        (const int4*)inv_index, inv_k, inv_c0, inv_c1, inv_c2, NI, iB,
        natoms, out);
}